// round 12
// baseline (speedup 1.0000x reference)
#include <cuda_runtime.h>

#define B_ 8
#define N_ 4096
#define KNN 20
#define PTS (B_*N_)
#define FULLMASK 0xFFFFFFFFu
typedef unsigned long long ull;

// ---------------- static device scratch (no allocation) ----------------
__device__ float2   g_xp[3*PTS];
__device__ float    g_xx[PTS];
__device__ float    g_nb[PTS*64];
__device__ float    g_cc[PTS*64];
__device__ int      g_idx[PTS*KNN];
__device__ float    g_m2[PTS*128];
__device__ float    g_s[2432];       // s1[64] ss1[64] s2[128] ss2[128] s3[1024] ss3[1024]
__device__ float    g_ab[384];       // a1[64] b1[64] a2[128] b2[128]
__device__ unsigned g_z3e[B_*1024];
__device__ float    g_g[B_*1024];
__device__ float    g_g4[B_*512];
__device__ float    g_mat[B_*9];
__device__ float    g_bias[B_*3];
__device__ int      g_c0 = 0;
__device__ int      g_c1 = 0;
__device__ int      g_c2 = 0;
// weight layouts for 4ch/thread compute (coalesced)
__device__ ulonglong2 g_w2n[32][64];        // [j][u]  u=(quad<<1)|chalf
__device__ ulonglong2 g_w3n[8][32][128];    // [chunk][j][t] t=(quad<<2)|cq

__device__ __forceinline__ float lrelu(float x){ return x >= 0.f ? x : 0.2f*x; }
__device__ __forceinline__ unsigned fenc(float f){
    unsigned u = __float_as_uint(f);
    return (u & 0x80000000u) ? ~u : (u | 0x80000000u);
}
__device__ __forceinline__ float fdec(unsigned u){
    u = (u & 0x80000000u) ? (u & 0x7FFFFFFFu) : ~u;
    return __uint_as_float(u);
}
__device__ __forceinline__ float f2lo(ull v){ return __uint_as_float((unsigned)v); }
__device__ __forceinline__ float f2hi(ull v){ return __uint_as_float((unsigned)(v>>32)); }
__device__ __forceinline__ void ffma2(ull& d, ull a, ull b){
    asm("fma.rn.f32x2 %0, %1, %2, %0;" : "+l"(d) : "l"(a), "l"(b));
}
__device__ __forceinline__ void fadd2(ull& d, ull b){
    asm("add.rn.f32x2 %0, %0, %1;" : "+l"(d) : "l"(b));
}

// ---------------- kernel 0: zero + SoA + norms + conv1 precompute + W layouts ----
__global__ void k_prep(const float* __restrict__ x, const float* __restrict__ w1,
                       const float* __restrict__ w2, const float* __restrict__ w3){
    __shared__ float wa[384], wd[384];
    int t = threadIdx.x;
    if (blockIdx.x == 0){
        for (int i = t; i < 2432; i += 256) g_s[i] = 0.f;
        for (int i = t; i < B_*1024; i += 256) g_z3e[i] = 0u;
    }
    for (int i = t; i < 384; i += 256){
        int o = i/6, c = i%6;
        float a = w1[o*12 + c];
        wa[i] = a;
        wd[i] = w1[o*12 + 6 + c] - a;
    }
    __syncthreads();

    int p = blockIdx.x*256 + t;            // 128 blocks x 256 = 32768
    // W3 layout: one 16B entry per thread
    {
        int chunk = p >> 12;
        int rem   = p & 4095;
        int j  = rem >> 7;       // 0..31
        int tt = rem & 127;
        int quad = tt >> 2, cq = tt & 3;
        int ch = chunk*128 + 4*quad + (j >> 3);
        int c  = cq*32 + (j & 7)*4;
        g_w3n[chunk][j][tt] = *(const ulonglong2*)(w3 + ch*128 + c);
    }
    // W2 layout: first 2048 threads
    if (p < 2048){
        int j = p >> 6, u = p & 63;
        int quad = u >> 1, chalf = u & 1;
        int ch = 4*quad + (j >> 3);
        int c  = chalf*32 + (j & 7)*4;
        g_w2n[j][u] = *(const ulonglong2*)(w2 + ch*64 + c);
    }
    {
        int b = p >> 12, n = p & 4095;
        const float* xb = x + b*6*N_ + n;
        float x0=xb[0], x1=xb[N_], x2=xb[2*N_], x3=xb[3*N_], x4=xb[4*N_], x5=xb[5*N_];
        g_xp[p]       = make_float2(x0,x1);
        g_xp[PTS+p]   = make_float2(x2,x3);
        g_xp[2*PTS+p] = make_float2(x4,x5);
        g_xx[p] = x0*x0+x1*x1+x2*x2+x3*x3+x4*x4+x5*x5;
    }
    int o = t & 63;
    int pbase = blockIdx.x*256;
    for (int pi = (t>>6); pi < 256; pi += 4){
        int pp = pbase + pi;
        int bb = pp >> 12, nn = pp & 4095;
        const float* xp = x + bb*6*N_ + nn;
        float y0=xp[0], y1=xp[N_], y2=xp[2*N_], y3=xp[3*N_], y4=xp[4*N_], y5=xp[5*N_];
        const float* A = wa + o*6;
        const float* D = wd + o*6;
        g_nb[pp*64+o] = y0*A[0]+y1*A[1]+y2*A[2]+y3*A[3]+y4*A[4]+y5*A[5];
        g_cc[pp*64+o] = y0*D[0]+y1*D[1]+y2*D[2]+y3*D[3]+y4*D[4]+y5*D[5];
    }
}

// ---------------- kernel 1: KNN top-20 (4 queries/warp, short insert chain) -------
__global__ void __launch_bounds__(512) k_knn(){
    int b   = blockIdx.x >> 6;
    int sec = blockIdx.x & 63;
    int w    = threadIdx.x >> 5;
    int lane = threadIdx.x & 31;
    int base = b*N_;
    const float2* xp0 = g_xp + base;
    const float2* xp1 = g_xp + PTS + base;
    const float2* xp2 = g_xp + 2*PTS + base;
    const float*  xxp = g_xx + base;

    int n0 = sec*64 + w*4;
    float q[4][6]; float lv[4]; int li[4]; float minv[4];
    #pragma unroll
    for (int j=0;j<4;j++){
        float2 a = xp0[n0+j], c = xp1[n0+j], e = xp2[n0+j];
        q[j][0]=a.x; q[j][1]=a.y; q[j][2]=c.x; q[j][3]=c.y; q[j][4]=e.x; q[j][5]=e.y;
        lv[j] = -3.4e38f; li[j] = 0; minv[j] = -3.4e38f;
    }

    for (int mb = 0; mb < N_; mb += 32){
        int m = mb + lane;
        float2 a = xp0[m], c = xp1[m], e = xp2[m];
        float xxm = xxp[m];
        float v[4];
        #pragma unroll
        for (int j=0;j<4;j++){
            float d = q[j][0]*a.x + q[j][1]*a.y + q[j][2]*c.x
                    + q[j][3]*c.y + q[j][4]*e.x + q[j][5]*e.y;
            v[j] = 2.f*d - xxm;
        }
        #pragma unroll
        for (int j=0;j<4;j++){
            unsigned cand = __ballot_sync(FULLMASK, v[j] > minv[j]);
            bool any = (cand != 0u);
            while (cand){
                int src = __ffs(cand)-1; cand &= cand-1;
                float cv = __shfl_sync(FULLMASK, v[j], src);
                float pv = __shfl_up_sync(FULLMASK, lv[j], 1);
                int   pq = __shfl_up_sync(FULLMASK, li[j], 1);
                unsigned lt = __ballot_sync(FULLMASK, lv[j] < cv) & 0xFFFFFu;
                if (lt){
                    int pos = __ffs(lt)-1;
                    if (lane > pos && lane < KNN){ lv[j]=pv; li[j]=pq; }
                    if (lane == pos)             { lv[j]=cv; li[j]=mb+src; }
                }
            }
            if (any) minv[j] = __shfl_sync(FULLMASK, lv[j], 19);
        }
    }
    #pragma unroll
    for (int j=0;j<4;j++)
        if (lane < KNN) g_idx[(base + n0 + j)*KNN + lane] = li[j];
}

// ---------------- kernel 2: z1 channel stats + bn1 finalize (last block) ----------------
__global__ void __launch_bounds__(256) k_stats1(const float* __restrict__ ga,
                                                const float* __restrict__ be){
    int t = threadIdx.x, o = t & 63, grp = t >> 6;
    float s = 0.f, ss = 0.f;
    for (int pi = blockIdx.x*4 + grp; pi < PTS; pi += 4096){
        float ccv = g_cc[pi*64 + o];
        int bbase = (pi >> 12) << 12;
        const int* ip = g_idx + pi*KNN;
        #pragma unroll
        for (int k=0;k<KNN;k++){
            int r = ip[k];
            float v = g_nb[(bbase + r)*64 + o] + ccv;
            s += v; ss += v*v;
        }
    }
    __shared__ float sh[256], sh2[256];
    sh[t] = s; sh2[t] = ss;
    __syncthreads();
    if (t < 64){
        atomicAdd(&g_s[t],    sh[t]+sh[t+64]+sh[t+128]+sh[t+192]);
        atomicAdd(&g_s[64+t], sh2[t]+sh2[t+64]+sh2[t+128]+sh2[t+192]);
    }
    __threadfence();
    __syncthreads();
    __shared__ int lastb;
    if (t == 0) lastb = (atomicAdd(&g_c0, 1) == (int)gridDim.x - 1);
    __syncthreads();
    if (lastb){
        if (t < 64){
            float cnt = (float)(PTS*KNN);
            float m = g_s[t]/cnt;
            float var = g_s[64+t]/cnt - m*m;
            float a = ga[t]*rsqrtf(var + 1e-5f);
            g_ab[t]    = a;
            g_ab[64+t] = be[t] - m*a;
        }
        if (t == 0) g_c0 = 0;
    }
}

// ---------------- kernel 3: conv2, 4 ch/thread, crossbar-balanced, 1 block/SM -------
// grid 148 persistent. Thread t: kh=t>>6 (k-half), u=t&63: quad=u>>1 (channels 4q..4q+3),
// chalf=u&1 (input c-half). Full z via shfl_xor(1); k-half max via smem mx.
#define C2_GRID 148
#define C2_TILES 2048
__global__ void __launch_bounds__(128) k_conv2(const float* __restrict__ ga,
                                               const float* __restrict__ be){
    int t = threadIdx.x;
    int kh = t >> 6;
    int u  = t & 63;
    int quad = u >> 1, chalf = u & 1;
    ull w[64];
    #pragma unroll
    for (int j=0;j<32;j++){
        ulonglong2 v = g_w2n[j][u]; w[2*j]=v.x; w[2*j+1]=v.y;
    }
    __shared__ __align__(16) float h1[4][20*64];    // 20KB
    __shared__ float4 mx[2][4][32];                 // [kh][pp][quad]
    float a1 = g_ab[u], b1 = g_ab[64+u];            // gather channel = u
    float s0=0.f,s1=0.f,s2=0.f,s3=0.f, t0=0.f,t1=0.f,t2=0.f,t3=0.f;

    for (int tile = blockIdx.x; tile < C2_TILES; tile += C2_GRID){
        int p0 = tile*16;
        for (int ph = 0; ph < 4; ++ph){
            int pb = p0 + ph*4;
            __syncthreads();
            // combine & store previous phase's maxes
            if (ph > 0 && kh == 0 && chalf == 0){
                #pragma unroll
                for (int pp=0;pp<4;pp++){
                    float4 a = mx[0][pp][quad], b = mx[1][pp][quad];
                    float4 v = make_float4(fmaxf(a.x,b.x), fmaxf(a.y,b.y),
                                           fmaxf(a.z,b.z), fmaxf(a.w,b.w));
                    *(float4*)(g_m2 + (pb-4+pp)*128 + quad*4) = v;
                }
            }
            // gather 4 points (thread role: k-half kh, channel u)
            #pragma unroll
            for (int pp=0;pp<4;pp++){
                int pi = pb + pp;
                int bbase = (pi >> 12) << 12;
                float ccv = g_cc[pi*64 + u];
                const int* ip = g_idx + pi*KNN;
                #pragma unroll
                for (int kk=0;kk<10;kk++){
                    int k = kh*10 + kk;
                    int r = ip[k];
                    h1[pp][k*64 + u] = lrelu(fmaf(a1, g_nb[(bbase+r)*64 + u] + ccv, b1));
                }
            }
            __syncthreads();
            // compute: 4 ch x 32 c x 10 k per thread
            #pragma unroll
            for (int pp=0;pp<4;pp++){
                float m0=-3.4e38f, m1=-3.4e38f, m2=-3.4e38f, m3=-3.4e38f;
                #pragma unroll
                for (int kk=0;kk<10;kk++){
                    int k = kh*10 + kk;
                    const ulonglong2* hp = (const ulonglong2*)(h1[pp] + k*64 + chalf*32);
                    ulonglong2 h[8];
                    #pragma unroll
                    for (int jj=0;jj<8;jj++) h[jj] = hp[jj];
                    ull A0=0,B0=0,A1=0,B1=0,A2=0,B2=0,A3=0,B3=0;
                    #pragma unroll
                    for (int jj=0;jj<8;jj++){
                        ffma2(A0, w[2*jj],      h[jj].x);
                        ffma2(B0, w[2*jj+1],    h[jj].y);
                        ffma2(A1, w[16+2*jj],   h[jj].x);
                        ffma2(B1, w[16+2*jj+1], h[jj].y);
                        ffma2(A2, w[32+2*jj],   h[jj].x);
                        ffma2(B2, w[32+2*jj+1], h[jj].y);
                        ffma2(A3, w[48+2*jj],   h[jj].x);
                        ffma2(B3, w[48+2*jj+1], h[jj].y);
                    }
                    fadd2(A0,B0); fadd2(A1,B1); fadd2(A2,B2); fadd2(A3,B3);
                    float z0 = f2lo(A0)+f2hi(A0);
                    float z1 = f2lo(A1)+f2hi(A1);
                    float z2 = f2lo(A2)+f2hi(A2);
                    float z3 = f2lo(A3)+f2hi(A3);
                    z0 += __shfl_xor_sync(FULLMASK, z0, 1);
                    z1 += __shfl_xor_sync(FULLMASK, z1, 1);
                    z2 += __shfl_xor_sync(FULLMASK, z2, 1);
                    z3 += __shfl_xor_sync(FULLMASK, z3, 1);
                    if (chalf == 0){
                        s0+=z0; t0+=z0*z0; m0=fmaxf(m0,z0);
                        s1+=z1; t1+=z1*z1; m1=fmaxf(m1,z1);
                        s2+=z2; t2+=z2*z2; m2=fmaxf(m2,z2);
                        s3+=z3; t3+=z3*z3; m3=fmaxf(m3,z3);
                    }
                }
                if (chalf == 0) mx[kh][pp][quad] = make_float4(m0,m1,m2,m3);
            }
        }
        __syncthreads();
        if (kh == 0 && chalf == 0){
            #pragma unroll
            for (int pp=0;pp<4;pp++){
                float4 a = mx[0][pp][quad], b = mx[1][pp][quad];
                float4 v = make_float4(fmaxf(a.x,b.x), fmaxf(a.y,b.y),
                                       fmaxf(a.z,b.z), fmaxf(a.w,b.w));
                *(float4*)(g_m2 + (p0+12+pp)*128 + quad*4) = v;
            }
        }
    }
    if (chalf == 0){
        int ch = 4*quad;
        atomicAdd(&g_s[128+ch],   s0); atomicAdd(&g_s[128+ch+1], s1);
        atomicAdd(&g_s[128+ch+2], s2); atomicAdd(&g_s[128+ch+3], s3);
        atomicAdd(&g_s[256+ch],   t0); atomicAdd(&g_s[256+ch+1], t1);
        atomicAdd(&g_s[256+ch+2], t2); atomicAdd(&g_s[256+ch+3], t3);
    }
    __threadfence();
    __syncthreads();
    __shared__ int lastb;
    if (t == 0) lastb = (atomicAdd(&g_c1, 1) == (int)gridDim.x - 1);
    __syncthreads();
    if (lastb){
        float cnt = (float)(PTS*KNN);
        float m = g_s[128+t]/cnt;
        float var = g_s[256+t]/cnt - m*m;
        float a = ga[t]*rsqrtf(var + 1e-5f);
        g_ab[128+t] = a;
        g_ab[256+t] = be[t] - m*a;
        if (t == 0) g_c1 = 0;
    }
}

// ---------------- kernel 4: conv3, 4 ch/thread, crossbar-balanced, 1 block/SM -------
// 2048 units: u = chunk(8) | bb(8) | sec(32); unit = 128 pts, 128 ch.
// Thread t: quad=t>>2 (channels chunk*128+4q..+3), cq=t&3 (input c-quarter).
#define C3_GRID 148
#define C3_UNITS 2048
__global__ void __launch_bounds__(128) k_conv3(const float* __restrict__ ga,
                                               const float* __restrict__ be){
    int t = threadIdx.x;
    int quad = t >> 2, cq = t & 3;
    __shared__ __align__(16) float h2[8*128];
    __shared__ float sab[128], sbb[128];
    sab[t] = g_ab[128+t]; sbb[t] = g_ab[256+t];
    __syncthreads();

    ull w[64];
    int curChunk = -1;
    for (int un = blockIdx.x; un < C3_UNITS; un += C3_GRID){
        int chunk = un & 7;
        int bb    = (un >> 3) & 7;
        int sec   = un >> 6;
        if (chunk != curChunk){
            #pragma unroll
            for (int j=0;j<32;j++){
                ulonglong2 v = g_w3n[chunk][j][t]; w[2*j]=v.x; w[2*j+1]=v.y;
            }
            curChunk = chunk;
        }
        float s0=0.f,s1=0.f,s2=0.f,s3=0.f, t0=0.f,t1=0.f,t2=0.f,t3=0.f;
        float m0=-3.4e38f,m1=-3.4e38f,m2=-3.4e38f,m3=-3.4e38f;
        int pbase = (bb << 12) + sec*128;
        for (int pp = 0; pp < 128; pp += 8){
            __syncthreads();
            #pragma unroll
            for (int r=0;r<8;r++)
                h2[r*128+t] = lrelu(fmaf(sab[t], g_m2[(pbase+pp+r)*128 + t], sbb[t]));
            __syncthreads();
            #pragma unroll
            for (int pl=0; pl<8; ++pl){
                const ulonglong2* hp = (const ulonglong2*)(h2 + pl*128 + cq*32);
                ulonglong2 h[8];
                #pragma unroll
                for (int jj=0;jj<8;jj++) h[jj] = hp[jj];
                ull A0=0,B0=0,A1=0,B1=0,A2=0,B2=0,A3=0,B3=0;
                #pragma unroll
                for (int jj=0;jj<8;jj++){
                    ffma2(A0, w[2*jj],      h[jj].x);
                    ffma2(B0, w[2*jj+1],    h[jj].y);
                    ffma2(A1, w[16+2*jj],   h[jj].x);
                    ffma2(B1, w[16+2*jj+1], h[jj].y);
                    ffma2(A2, w[32+2*jj],   h[jj].x);
                    ffma2(B2, w[32+2*jj+1], h[jj].y);
                    ffma2(A3, w[48+2*jj],   h[jj].x);
                    ffma2(B3, w[48+2*jj+1], h[jj].y);
                }
                fadd2(A0,B0); fadd2(A1,B1); fadd2(A2,B2); fadd2(A3,B3);
                float z0 = f2lo(A0)+f2hi(A0);
                float z1 = f2lo(A1)+f2hi(A1);
                float z2 = f2lo(A2)+f2hi(A2);
                float z3 = f2lo(A3)+f2hi(A3);
                z0 += __shfl_xor_sync(FULLMASK, z0, 1);
                z1 += __shfl_xor_sync(FULLMASK, z1, 1);
                z2 += __shfl_xor_sync(FULLMASK, z2, 1);
                z3 += __shfl_xor_sync(FULLMASK, z3, 1);
                z0 += __shfl_xor_sync(FULLMASK, z0, 2);
                z1 += __shfl_xor_sync(FULLMASK, z1, 2);
                z2 += __shfl_xor_sync(FULLMASK, z2, 2);
                z3 += __shfl_xor_sync(FULLMASK, z3, 2);
                if (cq == 0){
                    s0+=z0; t0+=z0*z0; m0=fmaxf(m0,z0);
                    s1+=z1; t1+=z1*z1; m1=fmaxf(m1,z1);
                    s2+=z2; t2+=z2*z2; m2=fmaxf(m2,z2);
                    s3+=z3; t3+=z3*z3; m3=fmaxf(m3,z3);
                }
            }
        }
        if (cq == 0){
            int ch = chunk*128 + 4*quad;
            atomicAdd(&g_s[384+ch],   s0); atomicAdd(&g_s[384+ch+1], s1);
            atomicAdd(&g_s[384+ch+2], s2); atomicAdd(&g_s[384+ch+3], s3);
            atomicAdd(&g_s[1408+ch],   t0); atomicAdd(&g_s[1408+ch+1], t1);
            atomicAdd(&g_s[1408+ch+2], t2); atomicAdd(&g_s[1408+ch+3], t3);
            atomicMax(&g_z3e[bb*1024 + ch],   fenc(m0));
            atomicMax(&g_z3e[bb*1024 + ch+1], fenc(m1));
            atomicMax(&g_z3e[bb*1024 + ch+2], fenc(m2));
            atomicMax(&g_z3e[bb*1024 + ch+3], fenc(m3));
        }
    }
    __threadfence();
    __syncthreads();
    __shared__ int lastb;
    if (t == 0) lastb = (atomicAdd(&g_c2, 1) == (int)gridDim.x - 1);
    __syncthreads();
    if (lastb){
        float cnt = (float)PTS;
        for (int c = t; c < 1024; c += 128){
            float m = g_s[384+c]/cnt;
            float var = g_s[1408+c]/cnt - m*m;
            float a = ga[c]*rsqrtf(var + 1e-5f);
            float bo = be[c] - m*a;
            #pragma unroll
            for (int b=0;b<B_;b++)
                g_g[b*1024+c] = lrelu(fmaf(a, fdec(g_z3e[b*1024+c]), bo));
        }
        if (t == 0) g_c2 = 0;
    }
}

// ---------------- kernel 5: fc1 + bn4 + lrelu ----------------
__global__ void __launch_bounds__(128) k_fc1(const float* __restrict__ fw,
                                             const float* __restrict__ g4g,
                                             const float* __restrict__ g4b){
    __shared__ float gs[B_*1024];
    int t = threadIdx.x;
    for (int i=t;i<B_*1024;i+=128) gs[i] = g_g[i];
    __syncthreads();
    int w = t >> 5, lane = t & 31;
    for (int jj=0;jj<2;jj++){
        int j = blockIdx.x*8 + w*2 + jj;
        const float* wrow = fw + j*1024;
        float acc[8] = {0,0,0,0,0,0,0,0};
        for (int c=lane;c<1024;c+=32){
            float wv = wrow[c];
            #pragma unroll
            for (int b=0;b<8;b++) acc[b] += gs[b*1024+c]*wv;
        }
        #pragma unroll
        for (int b=0;b<8;b++){
            #pragma unroll
            for (int off=16;off;off>>=1) acc[b] += __shfl_xor_sync(FULLMASK, acc[b], off);
        }
        if (lane == 0){
            float m=0.f;
            #pragma unroll
            for (int b=0;b<8;b++) m += acc[b];
            m *= 0.125f;
            float var=0.f;
            #pragma unroll
            for (int b=0;b<8;b++){ float d = acc[b]-m; var += d*d; }
            var *= 0.125f;
            float a = g4g[j]*rsqrtf(var + 1e-5f);
            float bo = g4b[j] - m*a;
            #pragma unroll
            for (int b=0;b<8;b++) g_g4[b*512+j] = lrelu(a*acc[b] + bo);
        }
    }
}

// ---------------- kernel 6: fc2+bn5+lrelu, fc3/fc4 -> mat/bias ----------------
__global__ void __launch_bounds__(256) k_head(const float* __restrict__ f2w,
        const float* __restrict__ g5g, const float* __restrict__ g5b,
        const float* __restrict__ f3w, const float* __restrict__ f3b,
        const float* __restrict__ f4w, const float* __restrict__ f4b){
    __shared__ float g4s[B_*512];
    __shared__ float g5s[B_*256];
    int t = threadIdx.x, w = t >> 5, lane = t & 31;
    for (int i=t;i<B_*512;i+=256) g4s[i] = g_g4[i];
    __syncthreads();
    for (int jj=0;jj<32;jj++){
        int j = w*32 + jj;
        const float* wrow = f2w + j*512;
        float acc[8] = {0,0,0,0,0,0,0,0};
        for (int c=lane;c<512;c+=32){
            float wv = wrow[c];
            #pragma unroll
            for (int b=0;b<8;b++) acc[b] += g4s[b*512+c]*wv;
        }
        #pragma unroll
        for (int b=0;b<8;b++){
            #pragma unroll
            for (int off=16;off;off>>=1) acc[b] += __shfl_xor_sync(FULLMASK, acc[b], off);
        }
        if (lane == 0){
            float m=0.f;
            #pragma unroll
            for (int b=0;b<8;b++) m += acc[b];
            m *= 0.125f;
            float var=0.f;
            #pragma unroll
            for (int b=0;b<8;b++){ float d = acc[b]-m; var += d*d; }
            var *= 0.125f;
            float a = g5g[j]*rsqrtf(var + 1e-5f);
            float bo = g5b[j] - m*a;
            #pragma unroll
            for (int b=0;b<8;b++) g5s[b*256+j] = lrelu(a*acc[b] + bo);
        }
    }
    __syncthreads();
    for (int i=0;i<12;i++){
        int task = w*12 + i;
        int b = task / 12, jo = task % 12;
        const float* wrow = (jo < 9) ? (f3w + jo*256) : (f4w + (jo-9)*256);
        float acc = 0.f;
        for (int c=lane;c<256;c+=32) acc += g5s[b*256+c]*wrow[c];
        #pragma unroll
        for (int off=16;off;off>>=1) acc += __shfl_xor_sync(FULLMASK, acc, off);
        if (lane == 0){
            if (jo < 9){
                int r = jo/3, cc = jo%3;
                g_mat[b*9+jo] = acc + f3b[jo] + (r==cc ? 1.f : 0.f);
            } else {
                g_bias[b*3 + (jo-9)] = acc + f4b[jo-9];
            }
        }
    }
}

// ---------------- kernel 7: apply 3x3 transform ----------------
__global__ void k_out(const float* __restrict__ x, float* __restrict__ out){
    int p = blockIdx.x*1024 + threadIdx.x;
    int b = p >> 12, n = p & 4095;
    const float* xb = x + b*6*N_ + n;
    float x0 = xb[0], x1 = xb[N_], x2 = xb[2*N_];
    const float* M  = g_mat + b*9;
    const float* Bi = g_bias + b*3;
    float* ob = out + b*3*N_ + n;
    ob[0]    = x0*M[0] + x1*M[3] + x2*M[6] + Bi[0];
    ob[N_]   = x0*M[1] + x1*M[4] + x2*M[7] + Bi[1];
    ob[2*N_] = x0*M[2] + x1*M[5] + x2*M[8] + Bi[2];
}

// ---------------- launch ----------------
extern "C" void kernel_launch(void* const* d_in, const int* in_sizes, int n_in,
                              void* d_out, int out_size){
    const float* x     = (const float*)d_in[0];
    const float* w1    = (const float*)d_in[1];
    const float* bn1g  = (const float*)d_in[2];
    const float* bn1b  = (const float*)d_in[3];
    const float* w2    = (const float*)d_in[4];
    const float* bn2g  = (const float*)d_in[5];
    const float* bn2b  = (const float*)d_in[6];
    const float* w3    = (const float*)d_in[7];
    const float* bn3g  = (const float*)d_in[8];
    const float* bn3b  = (const float*)d_in[9];
    const float* fc1w  = (const float*)d_in[10];
    const float* bn4g  = (const float*)d_in[11];
    const float* bn4b  = (const float*)d_in[12];
    const float* fc2w  = (const float*)d_in[13];
    const float* bn5g  = (const float*)d_in[14];
    const float* bn5b  = (const float*)d_in[15];
    const float* fc3w  = (const float*)d_in[16];
    const float* fc3b  = (const float*)d_in[17];
    const float* fc4w  = (const float*)d_in[18];
    const float* fc4b  = (const float*)d_in[19];
    float* out = (float*)d_out;

    k_prep  <<<128, 256>>>(x, w1, w2, w3);  // 1
    k_knn   <<<B_*64, 512>>>();             // 2
    k_stats1<<<1024, 256>>>(bn1g, bn1b);    // 3
    k_conv2 <<<C2_GRID, 128>>>(bn2g, bn2b); // 4  <- ncu capture slot
    k_conv3 <<<C3_GRID, 128>>>(bn3g, bn3b); // 5
    k_fc1   <<<64, 128>>>(fc1w, bn4g, bn4b);
    k_head  <<<1, 256>>>(fc2w, bn5g, bn5b, fc3w, fc3b, fc4w, fc4b);
    k_out   <<<32, 1024>>>(x, out);
}

// round 13
// speedup vs baseline: 1.4057x; 1.4057x over previous
#include <cuda_runtime.h>

#define B_ 8
#define N_ 4096
#define KNN 20
#define PTS (B_*N_)
#define FULLMASK 0xFFFFFFFFu
typedef unsigned long long ull;

// ---------------- static device scratch (no allocation) ----------------
__device__ float2   g_xp[3*PTS];
__device__ float    g_xx[PTS];
__device__ float    g_nb[PTS*64];
__device__ float    g_cc[PTS*64];
__device__ int      g_idx[PTS*KNN];
__device__ float    g_m2[PTS*128];
__device__ float    g_s[2432];       // s1[64] ss1[64] s2[128] ss2[128] s3[1024] ss3[1024]
__device__ float    g_ab[384];       // a1[64] b1[64] a2[128] b2[128]
__device__ unsigned g_z3e[B_*1024];
__device__ float    g_g[B_*1024];
__device__ float    g_g4[B_*512];
__device__ float    g_mat[B_*9];
__device__ float    g_bias[B_*3];
__device__ int      g_c0 = 0;
__device__ int      g_c1 = 0;
__device__ int      g_c2 = 0;
// weight layouts
__device__ ull        g_w2p[4096];         // [j][ch]: c-pair j of W2 row ch  (j<32, ch<128)
__device__ ulonglong2 g_w3t[8][32][128];   // [chunk][j2][t]  (R8 conv3 layout)

__device__ __forceinline__ float lrelu(float x){ return x >= 0.f ? x : 0.2f*x; }
__device__ __forceinline__ unsigned fenc(float f){
    unsigned u = __float_as_uint(f);
    return (u & 0x80000000u) ? ~u : (u | 0x80000000u);
}
__device__ __forceinline__ float fdec(unsigned u){
    u = (u & 0x80000000u) ? (u & 0x7FFFFFFFu) : ~u;
    return __uint_as_float(u);
}
__device__ __forceinline__ float f2lo(ull v){ return __uint_as_float((unsigned)v); }
__device__ __forceinline__ float f2hi(ull v){ return __uint_as_float((unsigned)(v>>32)); }
__device__ __forceinline__ void ffma2(ull& d, ull a, ull b){
    asm("fma.rn.f32x2 %0, %1, %2, %0;" : "+l"(d) : "l"(a), "l"(b));
}
__device__ __forceinline__ void fadd2(ull& d, ull b){
    asm("add.rn.f32x2 %0, %0, %1;" : "+l"(d) : "l"(b));
}

// ---------------- kernel 0: zero + SoA + norms + conv1 precompute + W layouts ----
__global__ void k_prep(const float* __restrict__ x, const float* __restrict__ w1,
                       const float* __restrict__ w2, const float* __restrict__ w3){
    __shared__ float wa[384], wd[384];
    int t = threadIdx.x;
    if (blockIdx.x == 0){
        for (int i = t; i < 2432; i += 256) g_s[i] = 0.f;
        for (int i = t; i < B_*1024; i += 256) g_z3e[i] = 0u;
    }
    for (int i = t; i < 384; i += 256){
        int o = i/6, c = i%6;
        float a = w1[o*12 + c];
        wa[i] = a;
        wd[i] = w1[o*12 + 6 + c] - a;
    }
    __syncthreads();

    int p = blockIdx.x*256 + t;            // 128 blocks x 256 = 32768
    // W3 layout (R8)
    {
        int chunk = p >> 12;
        int rem   = p & 4095;
        int j2 = rem >> 7;
        int tt = rem & 127;
        int kh = tt & 1, p2 = tt >> 1;
        int row = chunk*128 + 2*p2 + (j2 >= 16 ? 1 : 0);
        int j = j2 & 15;
        g_w3t[chunk][j2][tt] = ((const ulonglong2*)(w3 + row*128 + kh*64))[j];
    }
    // W2 c-pair layout: g_w2p[j*128+ch]
    if (p < 4096){
        int j = p >> 7, ch = p & 127;
        g_w2p[p] = ((const ull*)(w2 + ch*64))[j];
    }
    {
        int b = p >> 12, n = p & 4095;
        const float* xb = x + b*6*N_ + n;
        float x0=xb[0], x1=xb[N_], x2=xb[2*N_], x3=xb[3*N_], x4=xb[4*N_], x5=xb[5*N_];
        g_xp[p]       = make_float2(x0,x1);
        g_xp[PTS+p]   = make_float2(x2,x3);
        g_xp[2*PTS+p] = make_float2(x4,x5);
        g_xx[p] = x0*x0+x1*x1+x2*x2+x3*x3+x4*x4+x5*x5;
    }
    int o = t & 63;
    int pbase = blockIdx.x*256;
    for (int pi = (t>>6); pi < 256; pi += 4){
        int pp = pbase + pi;
        int bb = pp >> 12, nn = pp & 4095;
        const float* xp = x + bb*6*N_ + nn;
        float y0=xp[0], y1=xp[N_], y2=xp[2*N_], y3=xp[3*N_], y4=xp[4*N_], y5=xp[5*N_];
        const float* A = wa + o*6;
        const float* D = wd + o*6;
        g_nb[pp*64+o] = y0*A[0]+y1*A[1]+y2*A[2]+y3*A[3]+y4*A[4]+y5*A[5];
        g_cc[pp*64+o] = y0*D[0]+y1*D[1]+y2*D[2]+y3*D[3]+y4*D[4]+y5*D[5];
    }
}

// ---------------- kernel 1: KNN top-20 (4 queries/warp, short insert chain) -------
__global__ void __launch_bounds__(512) k_knn(){
    int b   = blockIdx.x >> 6;
    int sec = blockIdx.x & 63;
    int w    = threadIdx.x >> 5;
    int lane = threadIdx.x & 31;
    int base = b*N_;
    const float2* xp0 = g_xp + base;
    const float2* xp1 = g_xp + PTS + base;
    const float2* xp2 = g_xp + 2*PTS + base;
    const float*  xxp = g_xx + base;

    int n0 = sec*64 + w*4;
    float q[4][6]; float lv[4]; int li[4]; float minv[4];
    #pragma unroll
    for (int j=0;j<4;j++){
        float2 a = xp0[n0+j], c = xp1[n0+j], e = xp2[n0+j];
        q[j][0]=a.x; q[j][1]=a.y; q[j][2]=c.x; q[j][3]=c.y; q[j][4]=e.x; q[j][5]=e.y;
        lv[j] = -3.4e38f; li[j] = 0; minv[j] = -3.4e38f;
    }

    for (int mb = 0; mb < N_; mb += 32){
        int m = mb + lane;
        float2 a = xp0[m], c = xp1[m], e = xp2[m];
        float xxm = xxp[m];
        float v[4];
        #pragma unroll
        for (int j=0;j<4;j++){
            float d = q[j][0]*a.x + q[j][1]*a.y + q[j][2]*c.x
                    + q[j][3]*c.y + q[j][4]*e.x + q[j][5]*e.y;
            v[j] = 2.f*d - xxm;
        }
        #pragma unroll
        for (int j=0;j<4;j++){
            unsigned cand = __ballot_sync(FULLMASK, v[j] > minv[j]);
            bool any = (cand != 0u);
            while (cand){
                int src = __ffs(cand)-1; cand &= cand-1;
                float cv = __shfl_sync(FULLMASK, v[j], src);
                float pv = __shfl_up_sync(FULLMASK, lv[j], 1);
                int   pq = __shfl_up_sync(FULLMASK, li[j], 1);
                unsigned lt = __ballot_sync(FULLMASK, lv[j] < cv) & 0xFFFFFu;
                if (lt){
                    int pos = __ffs(lt)-1;
                    if (lane > pos && lane < KNN){ lv[j]=pv; li[j]=pq; }
                    if (lane == pos)             { lv[j]=cv; li[j]=mb+src; }
                }
            }
            if (any) minv[j] = __shfl_sync(FULLMASK, lv[j], 19);
        }
    }
    #pragma unroll
    for (int j=0;j<4;j++)
        if (lane < KNN) g_idx[(base + n0 + j)*KNN + lane] = li[j];
}

// ---------------- kernel 2: z1 channel stats + bn1 finalize (last block) ----------------
__global__ void __launch_bounds__(256) k_stats1(const float* __restrict__ ga,
                                                const float* __restrict__ be){
    int t = threadIdx.x, o = t & 63, grp = t >> 6;
    float s = 0.f, ss = 0.f;
    for (int pi = blockIdx.x*4 + grp; pi < PTS; pi += 4096){
        float ccv = g_cc[pi*64 + o];
        int bbase = (pi >> 12) << 12;
        const int* ip = g_idx + pi*KNN;
        #pragma unroll
        for (int k=0;k<KNN;k++){
            int r = ip[k];
            float v = g_nb[(bbase + r)*64 + o] + ccv;
            s += v; ss += v*v;
        }
    }
    __shared__ float sh[256], sh2[256];
    sh[t] = s; sh2[t] = ss;
    __syncthreads();
    if (t < 64){
        atomicAdd(&g_s[t],    sh[t]+sh[t+64]+sh[t+128]+sh[t+192]);
        atomicAdd(&g_s[64+t], sh2[t]+sh2[t+64]+sh2[t+128]+sh2[t+192]);
    }
    __threadfence();
    __syncthreads();
    __shared__ int lastb;
    if (t == 0) lastb = (atomicAdd(&g_c0, 1) == (int)gridDim.x - 1);
    __syncthreads();
    if (lastb){
        if (t < 64){
            float cnt = (float)(PTS*KNN);
            float m = g_s[t]/cnt;
            float var = g_s[64+t]/cnt - m*m;
            float a = ga[t]*rsqrtf(var + 1e-5f);
            g_ab[t]    = a;
            g_ab[64+t] = be[t] - m*a;
        }
        if (t == 0) g_c0 = 0;
    }
}

// ---------------- kernel 3: conv2 as smem-tiled GEMM ------------------------------
// grid 444 persistent, 128 threads. Tile = 2 points = 40 rows x 128 ch.
// Thread: rg=t&7 (rows rg*5..rg*5+4), cg=t>>3 (channels cg*8..cg*8+7).
// Weights in smem (c-pair layout), h tile 40x68 (padded). 13 LDS.128 : 80 FFMA2 per j2.
#define C2_GRID 444
#define C2_TILES (PTS/2)
__global__ void __launch_bounds__(128) k_conv2(const float* __restrict__ ga,
                                               const float* __restrict__ be){
    int t = threadIdx.x;
    int rg = t & 7, cg = t >> 3;
    int rbase = rg*5, ch0 = cg*8;
    __shared__ __align__(16) ull   swp[4096];      // 32KB  [j][ch]
    __shared__ __align__(16) float sh[40*68];      // 10.9KB padded
    __shared__ float sa1[64], sb1[64];
    for (int i = t; i < 4096; i += 128) swp[i] = g_w2p[i];
    if (t < 64){ sa1[t] = g_ab[t]; sb1[t] = g_ab[64+t]; }
    float s[8], ss[8];
    #pragma unroll
    for (int i=0;i<8;i++){ s[i]=0.f; ss[i]=0.f; }

    for (int tile = blockIdx.x; tile < C2_TILES; tile += C2_GRID){
        __syncthreads();          // previous compute done; safe to overwrite sh
        int bbase = ((tile*2) >> 12) << 12;
        const int* ip = g_idx + tile*40;
        const float* ccp = g_cc + tile*128;
        #pragma unroll
        for (int i=0;i<20;i++){
            int e = t + 128*i;
            int row = e >> 6, c = e & 63;
            int r = __ldg(&ip[row]);
            float v = g_nb[((bbase + r)<<6) + c] + __ldg(&ccp[((row>=20)<<6) + c]);
            sh[row*68 + c] = lrelu(fmaf(sa1[c], v, sb1[c]));
        }
        __syncthreads();
        ull acc[5][8];
        #pragma unroll
        for (int a=0;a<5;a++)
            #pragma unroll
            for (int b=0;b<8;b++) acc[a][b] = 0ull;
        #pragma unroll 8
        for (int j2=0;j2<16;j2++){
            ulonglong2 hv[5];
            #pragma unroll
            for (int rr=0;rr<5;rr++)
                hv[rr] = *(const ulonglong2*)(sh + (rbase+rr)*68 + j2*4);
            ulonglong2 wv0[4], wv1[4];
            #pragma unroll
            for (int cc=0;cc<4;cc++){
                wv0[cc] = *(const ulonglong2*)(swp + (2*j2)*128   + ch0 + 2*cc);
                wv1[cc] = *(const ulonglong2*)(swp + (2*j2+1)*128 + ch0 + 2*cc);
            }
            #pragma unroll
            for (int rr=0;rr<5;rr++){
                #pragma unroll
                for (int cc=0;cc<4;cc++){
                    ffma2(acc[rr][2*cc],   hv[rr].x, wv0[cc].x);
                    ffma2(acc[rr][2*cc+1], hv[rr].x, wv0[cc].y);
                    ffma2(acc[rr][2*cc],   hv[rr].y, wv1[cc].x);
                    ffma2(acc[rr][2*cc+1], hv[rr].y, wv1[cc].y);
                }
            }
        }
        float m[8];
        #pragma unroll
        for (int c8=0;c8<8;c8++) m[c8] = -3.4e38f;
        #pragma unroll
        for (int rr=0;rr<5;rr++){
            #pragma unroll
            for (int c8=0;c8<8;c8++){
                float z = f2lo(acc[rr][c8]) + f2hi(acc[rr][c8]);
                s[c8] += z; ss[c8] += z*z; m[c8] = fmaxf(m[c8], z);
            }
        }
        #pragma unroll
        for (int c8=0;c8<8;c8++){
            m[c8] = fmaxf(m[c8], __shfl_xor_sync(FULLMASK, m[c8], 1));
            m[c8] = fmaxf(m[c8], __shfl_xor_sync(FULLMASK, m[c8], 2));
        }
        if ((t & 3) == 0){
            int pp = (t >> 2) & 1;
            float* dst = g_m2 + (tile*2+pp)*128 + ch0;
            *(float4*)dst     = make_float4(m[0],m[1],m[2],m[3]);
            *(float4*)(dst+4) = make_float4(m[4],m[5],m[6],m[7]);
        }
    }
    #pragma unroll
    for (int c8=0;c8<8;c8++){
        atomicAdd(&g_s[128+ch0+c8], s[c8]);
        atomicAdd(&g_s[256+ch0+c8], ss[c8]);
    }
    __threadfence();
    __syncthreads();
    __shared__ int lastb;
    if (t == 0) lastb = (atomicAdd(&g_c1, 1) == (int)gridDim.x - 1);
    __syncthreads();
    if (lastb){
        float cnt = (float)(PTS*KNN);
        float mm = g_s[128+t]/cnt;
        float var = g_s[256+t]/cnt - mm*mm;
        float a = ga[t]*rsqrtf(var + 1e-5f);
        g_ab[128+t] = a;
        g_ab[256+t] = be[t] - mm*a;
        if (t == 0) g_c1 = 0;
    }
}

// ---------------- kernel 4: conv3, persistent (R8, measured) ----------------------
#define C3_UNITS 2048
__global__ void __launch_bounds__(128) k_conv3(const float* __restrict__ ga,
                                               const float* __restrict__ be){
    int t = threadIdx.x;
    int kh = t & 1;
    __shared__ __align__(16) float h2[8*128];
    __shared__ float sab[128], sbb[128];
    sab[t] = g_ab[128+t]; sbb[t] = g_ab[256+t];
    __syncthreads();

    for (int u = blockIdx.x; u < C3_UNITS; u += gridDim.x){
        int chunk = u & 7;
        int bb    = (u >> 3) & 7;
        int sec   = u >> 6;
        ull w0[32], w1[32];
        #pragma unroll
        for (int j=0;j<16;j++){
            ulonglong2 v0 = g_w3t[chunk][j][t];    w0[2*j]=v0.x; w0[2*j+1]=v0.y;
            ulonglong2 v1 = g_w3t[chunk][16+j][t]; w1[2*j]=v1.x; w1[2*j+1]=v1.y;
        }
        float s=0.f, ss=0.f, maxv=-3.4e38f;
        int pbase = (bb << 12) + sec*128;
        for (int pp = 0; pp < 128; pp += 8){
            __syncthreads();
            #pragma unroll
            for (int i = t; i < 8*128; i += 128){
                int pl = i >> 7, ch = i & 127;
                h2[i] = lrelu(fmaf(sab[ch], g_m2[(pbase+pp+pl)*128 + ch], sbb[ch]));
            }
            __syncthreads();
            #pragma unroll 2
            for (int pl=0; pl<8; ++pl){
                const ulonglong2* hp = (const ulonglong2*)(h2 + pl*128 + kh*64);
                ull A0=0ull, B0=0ull, A1=0ull, B1=0ull;
                #pragma unroll
                for (int j=0;j<16;j++){
                    ulonglong2 h = hp[j];
                    ffma2(A0, w0[2*j],   h.x);
                    ffma2(B0, w0[2*j+1], h.y);
                    ffma2(A1, w1[2*j],   h.x);
                    ffma2(B1, w1[2*j+1], h.y);
                }
                fadd2(A0, B0); fadd2(A1, B1);
                float z0p = f2lo(A0) + f2hi(A0);
                float z1p = f2lo(A1) + f2hi(A1);
                float z0 = z0p + __shfl_xor_sync(FULLMASK, z0p, 1);
                float z1 = z1p + __shfl_xor_sync(FULLMASK, z1p, 1);
                float z = kh ? z1 : z0;
                s += z; ss += z*z;
                maxv = fmaxf(maxv, z);
            }
        }
        int ch = chunk*128 + t;
        atomicAdd(&g_s[384+ch],  s);
        atomicAdd(&g_s[1408+ch], ss);
        atomicMax(&g_z3e[bb*1024 + ch], fenc(maxv));
    }
    __threadfence();
    __syncthreads();
    __shared__ int lastb;
    if (t == 0) lastb = (atomicAdd(&g_c2, 1) == (int)gridDim.x - 1);
    __syncthreads();
    if (lastb){
        float cnt = (float)PTS;
        for (int c = t; c < 1024; c += 128){
            float m = g_s[384+c]/cnt;
            float var = g_s[1408+c]/cnt - m*m;
            float a = ga[c]*rsqrtf(var + 1e-5f);
            float bo = be[c] - m*a;
            #pragma unroll
            for (int b=0;b<B_;b++)
                g_g[b*1024+c] = lrelu(fmaf(a, fdec(g_z3e[b*1024+c]), bo));
        }
        if (t == 0) g_c2 = 0;
    }
}

// ---------------- kernel 5: fc1 + bn4 + lrelu ----------------
__global__ void __launch_bounds__(128) k_fc1(const float* __restrict__ fw,
                                             const float* __restrict__ g4g,
                                             const float* __restrict__ g4b){
    __shared__ float gs[B_*1024];
    int t = threadIdx.x;
    for (int i=t;i<B_*1024;i+=128) gs[i] = g_g[i];
    __syncthreads();
    int w = t >> 5, lane = t & 31;
    for (int jj=0;jj<2;jj++){
        int j = blockIdx.x*8 + w*2 + jj;
        const float* wrow = fw + j*1024;
        float acc[8] = {0,0,0,0,0,0,0,0};
        for (int c=lane;c<1024;c+=32){
            float wv = wrow[c];
            #pragma unroll
            for (int b=0;b<8;b++) acc[b] += gs[b*1024+c]*wv;
        }
        #pragma unroll
        for (int b=0;b<8;b++){
            #pragma unroll
            for (int off=16;off;off>>=1) acc[b] += __shfl_xor_sync(FULLMASK, acc[b], off);
        }
        if (lane == 0){
            float m=0.f;
            #pragma unroll
            for (int b=0;b<8;b++) m += acc[b];
            m *= 0.125f;
            float var=0.f;
            #pragma unroll
            for (int b=0;b<8;b++){ float d = acc[b]-m; var += d*d; }
            var *= 0.125f;
            float a = g4g[j]*rsqrtf(var + 1e-5f);
            float bo = g4b[j] - m*a;
            #pragma unroll
            for (int b=0;b<8;b++) g_g4[b*512+j] = lrelu(a*acc[b] + bo);
        }
    }
}

// ---------------- kernel 6: fc2+bn5+lrelu, fc3/fc4 -> mat/bias ----------------
__global__ void __launch_bounds__(256) k_head(const float* __restrict__ f2w,
        const float* __restrict__ g5g, const float* __restrict__ g5b,
        const float* __restrict__ f3w, const float* __restrict__ f3b,
        const float* __restrict__ f4w, const float* __restrict__ f4b){
    __shared__ float g4s[B_*512];
    __shared__ float g5s[B_*256];
    int t = threadIdx.x, w = t >> 5, lane = t & 31;
    for (int i=t;i<B_*512;i+=256) g4s[i] = g_g4[i];
    __syncthreads();
    for (int jj=0;jj<32;jj++){
        int j = w*32 + jj;
        const float* wrow = f2w + j*512;
        float acc[8] = {0,0,0,0,0,0,0,0};
        for (int c=lane;c<512;c+=32){
            float wv = wrow[c];
            #pragma unroll
            for (int b=0;b<8;b++) acc[b] += g4s[b*512+c]*wv;
        }
        #pragma unroll
        for (int b=0;b<8;b++){
            #pragma unroll
            for (int off=16;off;off>>=1) acc[b] += __shfl_xor_sync(FULLMASK, acc[b], off);
        }
        if (lane == 0){
            float m=0.f;
            #pragma unroll
            for (int b=0;b<8;b++) m += acc[b];
            m *= 0.125f;
            float var=0.f;
            #pragma unroll
            for (int b=0;b<8;b++){ float d = acc[b]-m; var += d*d; }
            var *= 0.125f;
            float a = g5g[j]*rsqrtf(var + 1e-5f);
            float bo = g5b[j] - m*a;
            #pragma unroll
            for (int b=0;b<8;b++) g5s[b*256+j] = lrelu(a*acc[b] + bo);
        }
    }
    __syncthreads();
    for (int i=0;i<12;i++){
        int task = w*12 + i;
        int b = task / 12, jo = task % 12;
        const float* wrow = (jo < 9) ? (f3w + jo*256) : (f4w + (jo-9)*256);
        float acc = 0.f;
        for (int c=lane;c<256;c+=32) acc += g5s[b*256+c]*wrow[c];
        #pragma unroll
        for (int off=16;off;off>>=1) acc += __shfl_xor_sync(FULLMASK, acc, off);
        if (lane == 0){
            if (jo < 9){
                int r = jo/3, cc = jo%3;
                g_mat[b*9+jo] = acc + f3b[jo] + (r==cc ? 1.f : 0.f);
            } else {
                g_bias[b*3 + (jo-9)] = acc + f4b[jo-9];
            }
        }
    }
}

// ---------------- kernel 7: apply 3x3 transform ----------------
__global__ void k_out(const float* __restrict__ x, float* __restrict__ out){
    int p = blockIdx.x*1024 + threadIdx.x;
    int b = p >> 12, n = p & 4095;
    const float* xb = x + b*6*N_ + n;
    float x0 = xb[0], x1 = xb[N_], x2 = xb[2*N_];
    const float* M  = g_mat + b*9;
    const float* Bi = g_bias + b*3;
    float* ob = out + b*3*N_ + n;
    ob[0]    = x0*M[0] + x1*M[3] + x2*M[6] + Bi[0];
    ob[N_]   = x0*M[1] + x1*M[4] + x2*M[7] + Bi[1];
    ob[2*N_] = x0*M[2] + x1*M[5] + x2*M[8] + Bi[2];
}

// ---------------- launch ----------------
extern "C" void kernel_launch(void* const* d_in, const int* in_sizes, int n_in,
                              void* d_out, int out_size){
    const float* x     = (const float*)d_in[0];
    const float* w1    = (const float*)d_in[1];
    const float* bn1g  = (const float*)d_in[2];
    const float* bn1b  = (const float*)d_in[3];
    const float* w2    = (const float*)d_in[4];
    const float* bn2g  = (const float*)d_in[5];
    const float* bn2b  = (const float*)d_in[6];
    const float* w3    = (const float*)d_in[7];
    const float* bn3g  = (const float*)d_in[8];
    const float* bn3b  = (const float*)d_in[9];
    const float* fc1w  = (const float*)d_in[10];
    const float* bn4g  = (const float*)d_in[11];
    const float* bn4b  = (const float*)d_in[12];
    const float* fc2w  = (const float*)d_in[13];
    const float* bn5g  = (const float*)d_in[14];
    const float* bn5b  = (const float*)d_in[15];
    const float* fc3w  = (const float*)d_in[16];
    const float* fc3b  = (const float*)d_in[17];
    const float* fc4w  = (const float*)d_in[18];
    const float* fc4b  = (const float*)d_in[19];
    float* out = (float*)d_out;

    k_prep  <<<128, 256>>>(x, w1, w2, w3);  // 1
    k_knn   <<<B_*64, 512>>>();             // 2
    k_stats1<<<1024, 256>>>(bn1g, bn1b);    // 3
    k_conv2 <<<C2_GRID, 128>>>(bn2g, bn2b); // 4  <- ncu capture slot
    k_conv3 <<<444, 128>>>(bn3g, bn3b);     // 5
    k_fc1   <<<64, 128>>>(fc1w, bn4g, bn4b);
    k_head  <<<1, 256>>>(fc2w, bn5g, bn5b, fc3w, fc3b, fc4w, fc4b);
    k_out   <<<32, 1024>>>(x, out);
}

// round 14
// speedup vs baseline: 1.5350x; 1.0919x over previous
#include <cuda_runtime.h>

#define B_ 8
#define N_ 4096
#define KNN 20
#define PTS (B_*N_)
#define FULLMASK 0xFFFFFFFFu
typedef unsigned long long ull;

// ---------------- static device scratch (no allocation) ----------------
__device__ float2   g_xp[3*PTS];
__device__ float    g_xx[PTS];
__device__ float    g_nb[PTS*64];
__device__ float    g_cc[PTS*64];
__device__ int      g_idx[PTS*KNN];
__device__ float    g_m2[PTS*128];
__device__ float    g_s[2432];       // s1[64] ss1[64] s2[128] ss2[128] s3[1024] ss3[1024]
__device__ float    g_ab[384];       // a1[64] b1[64] a2[128] b2[128]
__device__ unsigned g_z3e[B_*1024];
__device__ float    g_g[B_*1024];
__device__ float    g_g4[B_*512];
__device__ float    g_mat[B_*9];
__device__ float    g_bias[B_*3];
__device__ int      g_c0 = 0;
__device__ int      g_c1 = 0;
__device__ int      g_c2 = 0;
// transposed weights for coalesced loads (R8 layouts)
__device__ ulonglong2 g_w2t[32][64];       // [j2][cp]
__device__ ulonglong2 g_w3t[8][32][128];   // [chunk][j2][t]

__device__ __forceinline__ float lrelu(float x){ return x >= 0.f ? x : 0.2f*x; }
__device__ __forceinline__ unsigned fenc(float f){
    unsigned u = __float_as_uint(f);
    return (u & 0x80000000u) ? ~u : (u | 0x80000000u);
}
__device__ __forceinline__ float fdec(unsigned u){
    u = (u & 0x80000000u) ? (u & 0x7FFFFFFFu) : ~u;
    return __uint_as_float(u);
}
__device__ __forceinline__ float f2lo(ull v){ return __uint_as_float((unsigned)v); }
__device__ __forceinline__ float f2hi(ull v){ return __uint_as_float((unsigned)(v>>32)); }
__device__ __forceinline__ void ffma2(ull& d, ull a, ull b){
    asm("fma.rn.f32x2 %0, %1, %2, %0;" : "+l"(d) : "l"(a), "l"(b));
}
__device__ __forceinline__ void fadd2(ull& d, ull b){
    asm("add.rn.f32x2 %0, %0, %1;" : "+l"(d) : "l"(b));
}

// ---------------- kernel 0: zero + SoA + norms + conv1 precompute + W transposes ----
__global__ void k_prep(const float* __restrict__ x, const float* __restrict__ w1,
                       const float* __restrict__ w2, const float* __restrict__ w3){
    __shared__ float wa[384], wd[384];
    int t = threadIdx.x;
    if (blockIdx.x == 0){
        for (int i = t; i < 2432; i += 256) g_s[i] = 0.f;
        for (int i = t; i < B_*1024; i += 256) g_z3e[i] = 0u;
    }
    for (int i = t; i < 384; i += 256){
        int o = i/6, c = i%6;
        float a = w1[o*12 + c];
        wa[i] = a;
        wd[i] = w1[o*12 + 6 + c] - a;
    }
    __syncthreads();

    int p = blockIdx.x*256 + t;            // 128 blocks x 256 = 32768
    // W3 transpose
    {
        int chunk = p >> 12;
        int rem   = p & 4095;
        int j2 = rem >> 7;
        int tt = rem & 127;
        int kh = tt & 1, p2 = tt >> 1;
        int row = chunk*128 + 2*p2 + (j2 >= 16 ? 1 : 0);
        int j = j2 & 15;
        g_w3t[chunk][j2][tt] = ((const ulonglong2*)(w3 + row*128 + kh*64))[j];
    }
    // W2 transpose
    if (p < 2048){
        int j2 = p >> 6, cp = p & 63;
        int row = 2*cp + (j2 >= 16 ? 1 : 0);
        int j = j2 & 15;
        g_w2t[j2][cp] = ((const ulonglong2*)(w2 + row*64))[j];
    }
    {
        int b = p >> 12, n = p & 4095;
        const float* xb = x + b*6*N_ + n;
        float x0=xb[0], x1=xb[N_], x2=xb[2*N_], x3=xb[3*N_], x4=xb[4*N_], x5=xb[5*N_];
        g_xp[p]       = make_float2(x0,x1);
        g_xp[PTS+p]   = make_float2(x2,x3);
        g_xp[2*PTS+p] = make_float2(x4,x5);
        g_xx[p] = x0*x0+x1*x1+x2*x2+x3*x3+x4*x4+x5*x5;
    }
    int o = t & 63;
    int pbase = blockIdx.x*256;
    for (int pi = (t>>6); pi < 256; pi += 4){
        int pp = pbase + pi;
        int bb = pp >> 12, nn = pp & 4095;
        const float* xp = x + bb*6*N_ + nn;
        float y0=xp[0], y1=xp[N_], y2=xp[2*N_], y3=xp[3*N_], y4=xp[4*N_], y5=xp[5*N_];
        const float* A = wa + o*6;
        const float* D = wd + o*6;
        g_nb[pp*64+o] = y0*A[0]+y1*A[1]+y2*A[2]+y3*A[3]+y4*A[4]+y5*A[5];
        g_cc[pp*64+o] = y0*D[0]+y1*D[1]+y2*D[2]+y3*D[3]+y4*D[4]+y5*D[5];
    }
}

// ---------------- kernel 1: KNN top-20 (4 queries/warp, short insert chain) -------
__global__ void __launch_bounds__(512) k_knn(){
    int b   = blockIdx.x >> 6;
    int sec = blockIdx.x & 63;
    int w    = threadIdx.x >> 5;
    int lane = threadIdx.x & 31;
    int base = b*N_;
    const float2* xp0 = g_xp + base;
    const float2* xp1 = g_xp + PTS + base;
    const float2* xp2 = g_xp + 2*PTS + base;
    const float*  xxp = g_xx + base;

    int n0 = sec*64 + w*4;
    float q[4][6]; float lv[4]; int li[4]; float minv[4];
    #pragma unroll
    for (int j=0;j<4;j++){
        float2 a = xp0[n0+j], c = xp1[n0+j], e = xp2[n0+j];
        q[j][0]=a.x; q[j][1]=a.y; q[j][2]=c.x; q[j][3]=c.y; q[j][4]=e.x; q[j][5]=e.y;
        lv[j] = -3.4e38f; li[j] = 0; minv[j] = -3.4e38f;
    }

    for (int mb = 0; mb < N_; mb += 32){
        int m = mb + lane;
        float2 a = xp0[m], c = xp1[m], e = xp2[m];
        float xxm = xxp[m];
        float v[4];
        #pragma unroll
        for (int j=0;j<4;j++){
            float d = q[j][0]*a.x + q[j][1]*a.y + q[j][2]*c.x
                    + q[j][3]*c.y + q[j][4]*e.x + q[j][5]*e.y;
            v[j] = 2.f*d - xxm;
        }
        #pragma unroll
        for (int j=0;j<4;j++){
            unsigned cand = __ballot_sync(FULLMASK, v[j] > minv[j]);
            bool any = (cand != 0u);
            while (cand){
                int src = __ffs(cand)-1; cand &= cand-1;
                float cv = __shfl_sync(FULLMASK, v[j], src);
                float pv = __shfl_up_sync(FULLMASK, lv[j], 1);
                int   pq = __shfl_up_sync(FULLMASK, li[j], 1);
                unsigned lt = __ballot_sync(FULLMASK, lv[j] < cv) & 0xFFFFFu;
                if (lt){
                    int pos = __ffs(lt)-1;
                    if (lane > pos && lane < KNN){ lv[j]=pv; li[j]=pq; }
                    if (lane == pos)             { lv[j]=cv; li[j]=mb+src; }
                }
            }
            if (any) minv[j] = __shfl_sync(FULLMASK, lv[j], 19);
        }
    }
    #pragma unroll
    for (int j=0;j<4;j++)
        if (lane < KNN) g_idx[(base + n0 + j)*KNN + lane] = li[j];
}

// ---------------- kernel 2: z1 channel stats + bn1 finalize (last block) ----------------
__global__ void __launch_bounds__(256) k_stats1(const float* __restrict__ ga,
                                                const float* __restrict__ be){
    int t = threadIdx.x, o = t & 63, grp = t >> 6;
    float s = 0.f, ss = 0.f;
    for (int pi = blockIdx.x*4 + grp; pi < PTS; pi += 4096){
        float ccv = g_cc[pi*64 + o];
        int bbase = (pi >> 12) << 12;
        const int* ip = g_idx + pi*KNN;
        #pragma unroll
        for (int k=0;k<KNN;k++){
            int r = ip[k];
            float v = g_nb[(bbase + r)*64 + o] + ccv;
            s += v; ss += v*v;
        }
    }
    __shared__ float sh[256], sh2[256];
    sh[t] = s; sh2[t] = ss;
    __syncthreads();
    if (t < 64){
        atomicAdd(&g_s[t],    sh[t]+sh[t+64]+sh[t+128]+sh[t+192]);
        atomicAdd(&g_s[64+t], sh2[t]+sh2[t+64]+sh2[t+128]+sh2[t+192]);
    }
    __threadfence();
    __syncthreads();
    __shared__ int lastb;
    if (t == 0) lastb = (atomicAdd(&g_c0, 1) == (int)gridDim.x - 1);
    __syncthreads();
    if (lastb){
        if (t < 64){
            float cnt = (float)(PTS*KNN);
            float m = g_s[t]/cnt;
            float var = g_s[64+t]/cnt - m*m;
            float a = ga[t]*rsqrtf(var + 1e-5f);
            g_ab[t]    = a;
            g_ab[64+t] = be[t] - m*a;
        }
        if (t == 0) g_c0 = 0;
    }
}

// ---------------- kernel 3: conv2, persistent (R8, measured 319us) ----------------
#define C2_TILES 2048
__global__ void __launch_bounds__(128) k_conv2(const float* __restrict__ ga,
                                               const float* __restrict__ be){
    int t = threadIdx.x;
    int kh = t >> 6;
    int cp = t & 63;
    ull w0[32], w1[32];
    #pragma unroll
    for (int j=0;j<16;j++){
        ulonglong2 v0 = g_w2t[j][cp];    w0[2*j]=v0.x; w0[2*j+1]=v0.y;
        ulonglong2 v1 = g_w2t[16+j][cp]; w1[2*j]=v1.x; w1[2*j+1]=v1.y;
    }
    __shared__ __align__(16) float h1[4][20*64];
    __shared__ float mx[2][4][128];
    float a1 = g_ab[cp], b1 = g_ab[64+cp];
    float s0=0.f, ss0=0.f, s1=0.f, ss1=0.f;

    for (int tile = blockIdx.x; tile < C2_TILES; tile += gridDim.x){
        int p0 = tile*16;
        for (int ph = 0; ph < 4; ++ph){
            int pb = p0 + ph*4;
            __syncthreads();
            if (ph > 0 && kh == 0){
                #pragma unroll
                for (int pp=0;pp<4;pp++){
                    int pi = pb - 4 + pp;
                    float2 v;
                    v.x = fmaxf(mx[0][pp][2*cp],   mx[1][pp][2*cp]);
                    v.y = fmaxf(mx[0][pp][2*cp+1], mx[1][pp][2*cp+1]);
                    *(float2*)(g_m2 + pi*128 + 2*cp) = v;
                }
            }
            #pragma unroll
            for (int pp=0;pp<4;pp++){
                int pi = pb + pp;
                int bbase = (pi >> 12) << 12;
                float ccv = g_cc[pi*64 + cp];
                const int* ip = g_idx + pi*KNN;
                #pragma unroll
                for (int kk=0;kk<10;kk++){
                    int k = kh*10 + kk;
                    int r = ip[k];
                    h1[pp][k*64 + cp] = lrelu(fmaf(a1, g_nb[(bbase + r)*64 + cp] + ccv, b1));
                }
            }
            __syncthreads();
            #pragma unroll
            for (int pp=0;pp<4;pp++){
                float m0 = -3.4e38f, m1 = -3.4e38f;
                for (int kk=0;kk<10;kk++){
                    int k = kh*10 + kk;
                    const ulonglong2* hp = (const ulonglong2*)(h1[pp] + k*64);
                    ull A0=0ull, B0=0ull, A1=0ull, B1=0ull;
                    #pragma unroll
                    for (int j=0;j<16;j++){
                        ulonglong2 h = hp[j];
                        ffma2(A0, w0[2*j],   h.x);
                        ffma2(B0, w0[2*j+1], h.y);
                        ffma2(A1, w1[2*j],   h.x);
                        ffma2(B1, w1[2*j+1], h.y);
                    }
                    fadd2(A0, B0); fadd2(A1, B1);
                    float z0 = f2lo(A0) + f2hi(A0);
                    float z1 = f2lo(A1) + f2hi(A1);
                    s0 += z0; ss0 += z0*z0; m0 = fmaxf(m0, z0);
                    s1 += z1; ss1 += z1*z1; m1 = fmaxf(m1, z1);
                }
                mx[kh][pp][2*cp]   = m0;
                mx[kh][pp][2*cp+1] = m1;
            }
        }
        __syncthreads();
        if (kh == 0){
            #pragma unroll
            for (int pp=0;pp<4;pp++){
                int pi = p0 + 12 + pp;
                float2 v;
                v.x = fmaxf(mx[0][pp][2*cp],   mx[1][pp][2*cp]);
                v.y = fmaxf(mx[0][pp][2*cp+1], mx[1][pp][2*cp+1]);
                *(float2*)(g_m2 + pi*128 + 2*cp) = v;
            }
        }
    }
    atomicAdd(&g_s[128+2*cp],   s0);
    atomicAdd(&g_s[128+2*cp+1], s1);
    atomicAdd(&g_s[256+2*cp],   ss0);
    atomicAdd(&g_s[256+2*cp+1], ss1);
    __threadfence();
    __syncthreads();
    __shared__ int lastb;
    if (t == 0) lastb = (atomicAdd(&g_c1, 1) == (int)gridDim.x - 1);
    __syncthreads();
    if (lastb){
        float cnt = (float)(PTS*KNN);
        float m = g_s[128+t]/cnt;
        float var = g_s[256+t]/cnt - m*m;
        float a = ga[t]*rsqrtf(var + 1e-5f);
        g_ab[128+t] = a;
        g_ab[256+t] = be[t] - m*a;
        if (t == 0) g_c1 = 0;
    }
}

// ---------------- kernel 4: conv3 with cp.async streaming double-buffer ------------
// 2048 units: u = chunk(8) | bb(8) | sec(32); unit = 128 pts; 8 phases of 16 pts.
// Pipeline: wait -> sync -> transform(par) -> sync -> issue(1-par) -> compute(par).
#define C3_UNITS 2048
__global__ void __launch_bounds__(128) k_conv3(const float* __restrict__ ga,
                                               const float* __restrict__ be){
    int t = threadIdx.x;
    int kh = t & 1;
    __shared__ __align__(16) float h2[2][16*128];   // 16KB double buffer
    __shared__ float sab[128], sbb[128];
    sab[t] = g_ab[128+t]; sbb[t] = g_ab[256+t];
    float a2 = g_ab[128+t], b2 = g_ab[256+t];
    __syncthreads();

    for (int u = blockIdx.x; u < C3_UNITS; u += gridDim.x){
        int chunk = u & 7;
        int bb    = (u >> 3) & 7;
        int sec   = u >> 6;            // 0..31
        ull w0[32], w1[32];
        #pragma unroll
        for (int j=0;j<16;j++){
            ulonglong2 v0 = g_w3t[chunk][j][t];    w0[2*j]=v0.x; w0[2*j+1]=v0.y;
            ulonglong2 v1 = g_w3t[chunk][16+j][t]; w1[2*j]=v1.x; w1[2*j+1]=v1.y;
        }
        float s=0.f, ss=0.f, maxv=-3.4e38f;
        int pbase = (bb << 12) + sec*128;
        const float4* src0 = (const float4*)(g_m2 + pbase*128);

        // prologue: issue phase 0 into buffer 0
        #pragma unroll
        for (int k4=0;k4<4;k4++){
            int i = t + 128*k4;        // 0..511 float4s = 16 rows
            unsigned dst = (unsigned)__cvta_generic_to_shared(&((float4*)h2[0])[i]);
            asm volatile("cp.async.ca.shared.global [%0], [%1], 16;\n"
                         :: "r"(dst), "l"(src0 + i));
        }
        asm volatile("cp.async.commit_group;\n");

        for (int ph = 0; ph < 8; ++ph){
            int par = ph & 1;
            asm volatile("cp.async.wait_group 0;\n");
            __syncthreads();
            // transform buffer par (all of a thread's elems have channel == t)
            #pragma unroll
            for (int k16=0;k16<16;k16++){
                float v = h2[par][k16*128 + t];
                h2[par][k16*128 + t] = lrelu(fmaf(a2, v, b2));
            }
            __syncthreads();
            if (ph < 7){
                const float4* srcn = (const float4*)(g_m2 + (pbase + (ph+1)*16)*128);
                #pragma unroll
                for (int k4=0;k4<4;k4++){
                    int i = t + 128*k4;
                    unsigned dst = (unsigned)__cvta_generic_to_shared(&((float4*)h2[1-par])[i]);
                    asm volatile("cp.async.ca.shared.global [%0], [%1], 16;\n"
                                 :: "r"(dst), "l"(srcn + i));
                }
                asm volatile("cp.async.commit_group;\n");
            }
            // compute 16 points on h2[par]
            #pragma unroll 2
            for (int pl=0; pl<16; ++pl){
                const ulonglong2* hp = (const ulonglong2*)(h2[par] + pl*128 + kh*64);
                ull A0=0ull, B0=0ull, A1=0ull, B1=0ull;
                #pragma unroll
                for (int j=0;j<16;j++){
                    ulonglong2 h = hp[j];
                    ffma2(A0, w0[2*j],   h.x);
                    ffma2(B0, w0[2*j+1], h.y);
                    ffma2(A1, w1[2*j],   h.x);
                    ffma2(B1, w1[2*j+1], h.y);
                }
                fadd2(A0, B0); fadd2(A1, B1);
                float z0p = f2lo(A0) + f2hi(A0);
                float z1p = f2lo(A1) + f2hi(A1);
                float z0 = z0p + __shfl_xor_sync(FULLMASK, z0p, 1);
                float z1 = z1p + __shfl_xor_sync(FULLMASK, z1p, 1);
                float z = kh ? z1 : z0;
                s += z; ss += z*z;
                maxv = fmaxf(maxv, z);
            }
        }
        int ch = chunk*128 + t;
        atomicAdd(&g_s[384+ch],  s);
        atomicAdd(&g_s[1408+ch], ss);
        atomicMax(&g_z3e[bb*1024 + ch], fenc(maxv));
        __syncthreads();   // all threads done with both buffers before next unit's issue
    }
    __threadfence();
    __syncthreads();
    __shared__ int lastb;
    if (t == 0) lastb = (atomicAdd(&g_c2, 1) == (int)gridDim.x - 1);
    __syncthreads();
    if (lastb){
        float cnt = (float)PTS;
        for (int c = t; c < 1024; c += 128){
            float m = g_s[384+c]/cnt;
            float var = g_s[1408+c]/cnt - m*m;
            float a = ga[c]*rsqrtf(var + 1e-5f);
            float bo = be[c] - m*a;
            #pragma unroll
            for (int b=0;b<B_;b++)
                g_g[b*1024+c] = lrelu(fmaf(a, fdec(g_z3e[b*1024+c]), bo));
        }
        if (t == 0) g_c2 = 0;
    }
}

// ---------------- kernel 5: fc1 + bn4 + lrelu ----------------
__global__ void __launch_bounds__(128) k_fc1(const float* __restrict__ fw,
                                             const float* __restrict__ g4g,
                                             const float* __restrict__ g4b){
    __shared__ float gs[B_*1024];
    int t = threadIdx.x;
    for (int i=t;i<B_*1024;i+=128) gs[i] = g_g[i];
    __syncthreads();
    int w = t >> 5, lane = t & 31;
    for (int jj=0;jj<2;jj++){
        int j = blockIdx.x*8 + w*2 + jj;
        const float* wrow = fw + j*1024;
        float acc[8] = {0,0,0,0,0,0,0,0};
        for (int c=lane;c<1024;c+=32){
            float wv = wrow[c];
            #pragma unroll
            for (int b=0;b<8;b++) acc[b] += gs[b*1024+c]*wv;
        }
        #pragma unroll
        for (int b=0;b<8;b++){
            #pragma unroll
            for (int off=16;off;off>>=1) acc[b] += __shfl_xor_sync(FULLMASK, acc[b], off);
        }
        if (lane == 0){
            float m=0.f;
            #pragma unroll
            for (int b=0;b<8;b++) m += acc[b];
            m *= 0.125f;
            float var=0.f;
            #pragma unroll
            for (int b=0;b<8;b++){ float d = acc[b]-m; var += d*d; }
            var *= 0.125f;
            float a = g4g[j]*rsqrtf(var + 1e-5f);
            float bo = g4b[j] - m*a;
            #pragma unroll
            for (int b=0;b<8;b++) g_g4[b*512+j] = lrelu(a*acc[b] + bo);
        }
    }
}

// ---------------- kernel 6: fc2+bn5+lrelu, fc3/fc4 -> mat/bias ----------------
__global__ void __launch_bounds__(256) k_head(const float* __restrict__ f2w,
        const float* __restrict__ g5g, const float* __restrict__ g5b,
        const float* __restrict__ f3w, const float* __restrict__ f3b,
        const float* __restrict__ f4w, const float* __restrict__ f4b){
    __shared__ float g4s[B_*512];
    __shared__ float g5s[B_*256];
    int t = threadIdx.x, w = t >> 5, lane = t & 31;
    for (int i=t;i<B_*512;i+=256) g4s[i] = g_g4[i];
    __syncthreads();
    for (int jj=0;jj<32;jj++){
        int j = w*32 + jj;
        const float* wrow = f2w + j*512;
        float acc[8] = {0,0,0,0,0,0,0,0};
        for (int c=lane;c<512;c+=32){
            float wv = wrow[c];
            #pragma unroll
            for (int b=0;b<8;b++) acc[b] += g4s[b*512+c]*wv;
        }
        #pragma unroll
        for (int b=0;b<8;b++){
            #pragma unroll
            for (int off=16;off;off>>=1) acc[b] += __shfl_xor_sync(FULLMASK, acc[b], off);
        }
        if (lane == 0){
            float m=0.f;
            #pragma unroll
            for (int b=0;b<8;b++) m += acc[b];
            m *= 0.125f;
            float var=0.f;
            #pragma unroll
            for (int b=0;b<8;b++){ float d = acc[b]-m; var += d*d; }
            var *= 0.125f;
            float a = g5g[j]*rsqrtf(var + 1e-5f);
            float bo = g5b[j] - m*a;
            #pragma unroll
            for (int b=0;b<8;b++) g5s[b*256+j] = lrelu(a*acc[b] + bo);
        }
    }
    __syncthreads();
    for (int i=0;i<12;i++){
        int task = w*12 + i;
        int b = task / 12, jo = task % 12;
        const float* wrow = (jo < 9) ? (f3w + jo*256) : (f4w + (jo-9)*256);
        float acc = 0.f;
        for (int c=lane;c<256;c+=32) acc += g5s[b*256+c]*wrow[c];
        #pragma unroll
        for (int off=16;off;off>>=1) acc += __shfl_xor_sync(FULLMASK, acc, off);
        if (lane == 0){
            if (jo < 9){
                int r = jo/3, cc = jo%3;
                g_mat[b*9+jo] = acc + f3b[jo] + (r==cc ? 1.f : 0.f);
            } else {
                g_bias[b*3 + (jo-9)] = acc + f4b[jo-9];
            }
        }
    }
}

// ---------------- kernel 7: apply 3x3 transform ----------------
__global__ void k_out(const float* __restrict__ x, float* __restrict__ out){
    int p = blockIdx.x*1024 + threadIdx.x;
    int b = p >> 12, n = p & 4095;
    const float* xb = x + b*6*N_ + n;
    float x0 = xb[0], x1 = xb[N_], x2 = xb[2*N_];
    const float* M  = g_mat + b*9;
    const float* Bi = g_bias + b*3;
    float* ob = out + b*3*N_ + n;
    ob[0]    = x0*M[0] + x1*M[3] + x2*M[6] + Bi[0];
    ob[N_]   = x0*M[1] + x1*M[4] + x2*M[7] + Bi[1];
    ob[2*N_] = x0*M[2] + x1*M[5] + x2*M[8] + Bi[2];
}

// ---------------- launch ----------------
extern "C" void kernel_launch(void* const* d_in, const int* in_sizes, int n_in,
                              void* d_out, int out_size){
    const float* x     = (const float*)d_in[0];
    const float* w1    = (const float*)d_in[1];
    const float* bn1g  = (const float*)d_in[2];
    const float* bn1b  = (const float*)d_in[3];
    const float* w2    = (const float*)d_in[4];
    const float* bn2g  = (const float*)d_in[5];
    const float* bn2b  = (const float*)d_in[6];
    const float* w3    = (const float*)d_in[7];
    const float* bn3g  = (const float*)d_in[8];
    const float* bn3b  = (const float*)d_in[9];
    const float* fc1w  = (const float*)d_in[10];
    const float* bn4g  = (const float*)d_in[11];
    const float* bn4b  = (const float*)d_in[12];
    const float* fc2w  = (const float*)d_in[13];
    const float* bn5g  = (const float*)d_in[14];
    const float* bn5b  = (const float*)d_in[15];
    const float* fc3w  = (const float*)d_in[16];
    const float* fc3b  = (const float*)d_in[17];
    const float* fc4w  = (const float*)d_in[18];
    const float* fc4b  = (const float*)d_in[19];
    float* out = (float*)d_out;

    k_prep  <<<128, 256>>>(x, w1, w2, w3);  // 1
    k_knn   <<<B_*64, 512>>>();             // 2
    k_stats1<<<1024, 256>>>(bn1g, bn1b);    // 3
    k_conv2 <<<444, 128>>>(bn2g, bn2b);     // 4  <- ncu capture slot (revert check)
    k_conv3 <<<444, 128>>>(bn3g, bn3b);     // 5
    k_fc1   <<<64, 128>>>(fc1w, bn4g, bn4b);
    k_head  <<<1, 256>>>(fc2w, bn5g, bn5b, fc3w, fc3b, fc4w, fc4b);
    k_out   <<<32, 1024>>>(x, out);
}